// round 16
// baseline (speedup 1.0000x reference)
#include <cuda_runtime.h>
#include <cuda_fp16.h>
#include <math.h>
#include <stdint.h>

#define MAXN   100000
#define MAXE   1600000
#define FEAT   128
#define COUT   64

#define CSR_BLOCKS  256
#define CSR_THREADS 512

// ---------------------------------------------------------------------------
// Scratch (device globals — no allocations allowed)
// ---------------------------------------------------------------------------
__device__ __half   g_h16[MAXN * FEAT];
__device__ __half   g_o1 [MAXN * FEAT];
__device__ __half   g_o2 [MAXN * FEAT];
__device__ float    g_ssrc[MAXN];
__device__ float    g_sdst[MAXN];
__device__ float    g_es  [MAXN];
__device__ int      g_edges[2 * MAXE];
__device__ int      g_rowptr[MAXN + 1];
__device__ int      g_csr_src[MAXE];
__device__ int      g_deg [MAXN];
__device__ int      g_fill[MAXN];
__device__ int      g_bsum[CSR_BLOCKS];
__device__ unsigned g_bar[8];
__device__ int      g_is64;
// k-pair-packed fp16 weights: Wpk[kp*cols + col] = half2(W[2kp][col], W[2kp+1][col])
__device__ uint32_t g_w1pk[(FEAT / 2) * FEAT];
__device__ uint32_t g_w2pk[(FEAT / 2) * FEAT];
__device__ uint32_t g_wlpk[(FEAT / 2) * COUT];

// ---------------------------------------------------------------------------
// fp16 helpers
// ---------------------------------------------------------------------------
__device__ __forceinline__ uint32_t pack_half2(float a, float b) {
    __half2 h = __floats2half2_rn(a, b);
    return *reinterpret_cast<uint32_t*>(&h);
}

// Pre-pack W1, W2 (128x128) and Wl (128x64) into k-pair fp16 layout. One launch.
__global__ void pack_weights(const float* __restrict__ W1,
                             const float* __restrict__ W2,
                             const float* __restrict__ Wl) {
    int i = blockIdx.x * blockDim.x + threadIdx.x;
    const int nW = (FEAT / 2) * FEAT;      // 8192 per square weight
    const int nL = (FEAT / 2) * COUT;      // 4096
    if (i < nW) {
        int kp = i >> 7, col = i & 127;
        g_w1pk[i] = pack_half2(W1[(2 * kp) * FEAT + col], W1[(2 * kp + 1) * FEAT + col]);
    } else if (i < 2 * nW) {
        int j = i - nW;
        int kp = j >> 7, col = j & 127;
        g_w2pk[j] = pack_half2(W2[(2 * kp) * FEAT + col], W2[(2 * kp + 1) * FEAT + col]);
    } else if (i < 2 * nW + nL) {
        int j = i - 2 * nW;
        int kp = j >> 6, col = j & 63;
        g_wlpk[j] = pack_half2(Wl[(2 * kp) * COUT + col], Wl[(2 * kp + 1) * COUT + col]);
    }
}

// ---------------------------------------------------------------------------
// Fused CSR build (detect + convert + count + scan + fill + tail copy)
// ---------------------------------------------------------------------------
__device__ __forceinline__ void grid_barrier(int id) {
    __syncthreads();
    if (threadIdx.x == 0) {
        unsigned arrived = atomicAdd(&g_bar[id], 1u) + 1u;
        if (arrived < gridDim.x) {
            while (*(volatile unsigned*)&g_bar[id] < gridDim.x) __nanosleep(64);
        }
    }
    __syncthreads();
}

__global__ void __launch_bounds__(CSR_THREADS, 4)
csr_build(const void* ei, int N, int E, int ncheck, float* tailf) {
    __shared__ int swarp[CSR_THREADS / 32];
    const int tid = threadIdx.x;
    const int gid = blockIdx.x * CSR_THREADS + tid;
    const int stride = gridDim.x * CSR_THREADS;
    const int lane = tid & 31;
    const int warp = tid >> 5;

    int ok = 1;
    const long long* p64 = (const long long*)ei;
    for (int i = tid; i < ncheck; i += CSR_THREADS) {
        long long v = p64[i];
        if (v < 0 || v >= (long long)N) ok = 0;
    }
    const int is64 = __syncthreads_and(ok);
    if (gid == 0) g_is64 = is64;

    for (int i = gid; i < 2 * E; i += stride) {
        int v;
        if (is64) v = (int)p64[i];
        else      v = ((const int*)ei)[i];
        g_edges[i] = v;
        if (tailf) tailf[i] = (float)v;
        if (i >= E) atomicAdd(&g_deg[v], 1);
    }
    grid_barrier(0);

    int v = (gid < N) ? g_deg[gid] : 0;
    int x = v;
#pragma unroll
    for (int o = 1; o < 32; o <<= 1) {
        int y = __shfl_up_sync(0xffffffffu, x, o);
        if (lane >= o) x += y;
    }
    if (lane == 31) swarp[warp] = x;
    __syncthreads();
    if (warp == 0) {
        int s = (lane < CSR_THREADS / 32) ? swarp[lane] : 0;
#pragma unroll
        for (int o = 1; o < 32; o <<= 1) {
            int y = __shfl_up_sync(0xffffffffu, s, o);
            if (lane >= o) s += y;
        }
        if (lane < CSR_THREADS / 32) swarp[lane] = s;
    }
    __syncthreads();
    int incl = x + (warp ? swarp[warp - 1] : 0);
    if (tid == CSR_THREADS - 1) g_bsum[blockIdx.x] = incl;
    grid_barrier(1);

    {
        __shared__ int sred[CSR_THREADS / 32];
        int p = 0;
        for (int j = tid; j < (int)blockIdx.x; j += CSR_THREADS) p += g_bsum[j];
#pragma unroll
        for (int o = 16; o; o >>= 1) p += __shfl_xor_sync(0xffffffffu, p, o);
        if (lane == 0) sred[warp] = p;
        __syncthreads();
        if (warp == 0) {
            int q = (lane < CSR_THREADS / 32) ? sred[lane] : 0;
#pragma unroll
            for (int o = 16; o; o >>= 1) q += __shfl_xor_sync(0xffffffffu, q, o);
            if (lane == 0) sred[0] = q;
        }
        __syncthreads();
        int bpref = sred[0];
        if (gid < N) g_rowptr[gid] = bpref + incl - v;
        if (gid == N) g_rowptr[N] = E;
    }
    grid_barrier(2);

    for (int e = gid; e < E; e += stride) {
        int d = g_edges[E + e];
        int pos = g_rowptr[d] + atomicAdd(&g_fill[d], 1);
        g_csr_src[pos] = g_edges[e];
    }
}

// ---------------------------------------------------------------------------
// fp16 HMMA
// ---------------------------------------------------------------------------
__device__ __forceinline__ void mma_f16(float4& c, const uint32_t a[4], const uint32_t b[2]) {
    asm volatile(
        "mma.sync.aligned.m16n8k16.row.col.f32.f16.f16.f32 "
        "{%0,%1,%2,%3}, {%4,%5,%6,%7}, {%8,%9}, {%0,%1,%2,%3};\n"
        : "+f"(c.x), "+f"(c.y), "+f"(c.z), "+f"(c.w)
        : "r"(a[0]), "r"(a[1]), "r"(a[2]), "r"(a[3]), "r"(b[0]), "r"(b[1]));
}

#define GBM 128
#define GBK 32
#define NKI (FEAT / GBK)
#define ASTR 20
#define BSTR 136
#define BSTRF 72

// h16[N,128] = fp16(A[N,128] @ W[128,128]); fused scores. Double-buffered.
__global__ void __launch_bounds__(256, 2)
gemm_f16(const void* __restrict__ A, int a_half,
         const uint32_t* __restrict__ Wpk,
         const float* __restrict__ a_src, const float* __restrict__ a_dst,
         __half* __restrict__ H16, int N) {
    __shared__ uint32_t As[2][GBM][ASTR];
    __shared__ uint32_t Bs[2][GBK / 2][BSTR];
    __shared__ float sAs[FEAT], sAd[FEAT];
    __shared__ float redS[GBM][2], redD[GBM][2];

    int t = threadIdx.x;
    int wid = t >> 5, lane = t & 31;
    int wm = wid >> 1, wn = wid & 1;
    int rowBase = blockIdx.x * GBM;
    int lg = lane >> 2;
    int lt = lane & 3;

    if (t < FEAT) { sAs[t] = a_src[t]; sAd[t] = a_dst[t]; }

    float4 c[2][8];
#pragma unroll
    for (int mt = 0; mt < 2; mt++)
#pragma unroll
        for (int nt = 0; nt < 8; nt++) c[mt][nt] = make_float4(0.f, 0.f, 0.f, 0.f);

    int arow = t >> 3;
    int acol = (t & 7) * 4;
    int bkp  = t >> 5;

    auto load_stage = [&](int ki, int b) {
        int kk = ki * GBK;
#pragma unroll
        for (int v = 0; v < 4; v++) {
            int r = arow + v * 32;
            int gr = rowBase + r;
            if (a_half) {
                uint2 u = make_uint2(0u, 0u);
                if (gr < N) u = *(const uint2*)((const __half*)A + (size_t)gr * FEAT + kk + acol);
                As[b][r][(acol >> 1) + 0] = u.x;
                As[b][r][(acol >> 1) + 1] = u.y;
            } else {
                float4 av = make_float4(0.f, 0.f, 0.f, 0.f);
                if (gr < N) av = *(const float4*)((const float*)A + (size_t)gr * FEAT + kk + acol);
                As[b][r][(acol >> 1) + 0] = pack_half2(av.x, av.y);
                As[b][r][(acol >> 1) + 1] = pack_half2(av.z, av.w);
            }
        }
        int kp0 = kk >> 1;
#pragma unroll
        for (int v = 0; v < 2; v++) {
            int kp = bkp + v * 8;
            const uint32_t* wrow = Wpk + (size_t)(kp0 + kp) * FEAT;
#pragma unroll
            for (int j = 0; j < 4; j++) {
                int col = lane + 32 * j;
                Bs[b][kp][col] = wrow[col];
            }
        }
    };

    load_stage(0, 0);
#pragma unroll
    for (int ki = 0; ki < NKI; ki++) {
        int buf = ki & 1;
        __syncthreads();
        if (ki < NKI - 1) load_stage(ki + 1, buf ^ 1);
#pragma unroll
        for (int ks = 0; ks < 2; ks++) {
            int k0h = ks * 8;
            uint32_t af[2][4];
#pragma unroll
            for (int mt = 0; mt < 2; mt++) {
                int row = wm * 32 + mt * 16 + lg;
                af[mt][0] = As[buf][row][k0h + lt];
                af[mt][1] = As[buf][row + 8][k0h + lt];
                af[mt][2] = As[buf][row][k0h + lt + 4];
                af[mt][3] = As[buf][row + 8][k0h + lt + 4];
            }
            uint32_t bf[8][2];
#pragma unroll
            for (int nt = 0; nt < 8; nt++) {
                int col = wn * 64 + nt * 8 + lg;
                bf[nt][0] = Bs[buf][k0h + lt][col];
                bf[nt][1] = Bs[buf][k0h + lt + 4][col];
            }
#pragma unroll
            for (int mt = 0; mt < 2; mt++)
#pragma unroll
                for (int nt = 0; nt < 8; nt++)
                    mma_f16(c[mt][nt], af[mt], bf[nt]);
        }
    }

    // epilogue: fp16 store + fused score partials
#pragma unroll
    for (int mt = 0; mt < 2; mt++) {
        int rl0 = wm * 32 + mt * 16 + lg;
        int row0 = rowBase + rl0;
        float pS0 = 0.f, pS8 = 0.f, pD0 = 0.f, pD8 = 0.f;
#pragma unroll
        for (int nt = 0; nt < 8; nt++) {
            int col = wn * 64 + nt * 8 + lt * 2;
            float as0 = sAs[col], as1 = sAs[col + 1];
            float ad0 = sAd[col], ad1 = sAd[col + 1];
            pS0 += c[mt][nt].x * as0 + c[mt][nt].y * as1;
            pD0 += c[mt][nt].x * ad0 + c[mt][nt].y * ad1;
            pS8 += c[mt][nt].z * as0 + c[mt][nt].w * as1;
            pD8 += c[mt][nt].z * ad0 + c[mt][nt].w * ad1;
            if (row0 < N)
                *(__half2*)(H16 + (size_t)row0 * FEAT + col) = __floats2half2_rn(c[mt][nt].x, c[mt][nt].y);
            if (row0 + 8 < N)
                *(__half2*)(H16 + (size_t)(row0 + 8) * FEAT + col) = __floats2half2_rn(c[mt][nt].z, c[mt][nt].w);
        }
#pragma unroll
        for (int o = 1; o < 4; o <<= 1) {
            pS0 += __shfl_xor_sync(0xffffffffu, pS0, o);
            pS8 += __shfl_xor_sync(0xffffffffu, pS8, o);
            pD0 += __shfl_xor_sync(0xffffffffu, pD0, o);
            pD8 += __shfl_xor_sync(0xffffffffu, pD8, o);
        }
        if (lt == 0) {
            redS[rl0][wn] = pS0;      redD[rl0][wn] = pD0;
            redS[rl0 + 8][wn] = pS8;  redD[rl0 + 8][wn] = pD8;
        }
    }
    __syncthreads();
    if (t < GBM) {
        int grow = rowBase + t;
        if (grow < N) {
            float s1 = redS[t][0] + redS[t][1];
            float s2 = redD[t][0] + redD[t][1];
            g_ssrc[grow] = s1;
            g_sdst[grow] = s2;
            float e = s1 + s2;
            g_es[grow] = e > 0.f ? e : 0.2f * e;
        }
    }
}

// ---------------------------------------------------------------------------
// Final: L = (o1+o2) @ Wl + bl, fused log-softmax. Double-buffered, Wl packed.
// ---------------------------------------------------------------------------
__global__ void __launch_bounds__(256, 2)
gemm_f16_final(const __half* __restrict__ A1, const __half* __restrict__ A2,
               const uint32_t* __restrict__ Wpk, const float* __restrict__ bl,
               float* __restrict__ out, int N) {
    __shared__ union SmU {
        struct { uint32_t As[2][GBM][ASTR]; uint32_t Bs[2][GBK / 2][BSTRF]; } mm;
        float logits[GBM][COUT + 2];
    } sm;

    int t = threadIdx.x;
    int wid = t >> 5, lane = t & 31;
    int wm = wid >> 1, wn = wid & 1;
    int rowBase = blockIdx.x * GBM;
    int lg = lane >> 2;
    int lt = lane & 3;

    float4 c[2][4];
#pragma unroll
    for (int mt = 0; mt < 2; mt++)
#pragma unroll
        for (int nt = 0; nt < 4; nt++) c[mt][nt] = make_float4(0.f, 0.f, 0.f, 0.f);

    int arow = t >> 3;
    int acol = (t & 7) * 4;
    int bkp  = t >> 4;
    int bl16 = t & 15;

    auto load_stage = [&](int ki, int b) {
        int kk = ki * GBK;
#pragma unroll
        for (int v = 0; v < 4; v++) {
            int r = arow + v * 32;
            int gr = rowBase + r;
            uint32_t p0 = 0u, p1 = 0u;
            if (gr < N) {
                uint2 u1 = *(const uint2*)(A1 + (size_t)gr * FEAT + kk + acol);
                uint2 u2 = *(const uint2*)(A2 + (size_t)gr * FEAT + kk + acol);
                float2 a0 = __half22float2(*(__half2*)&u1.x);
                float2 a1 = __half22float2(*(__half2*)&u1.y);
                float2 b0 = __half22float2(*(__half2*)&u2.x);
                float2 b1 = __half22float2(*(__half2*)&u2.y);
                p0 = pack_half2(a0.x + b0.x, a0.y + b0.y);
                p1 = pack_half2(a1.x + b1.x, a1.y + b1.y);
            }
            sm.mm.As[b][r][(acol >> 1) + 0] = p0;
            sm.mm.As[b][r][(acol >> 1) + 1] = p1;
        }
        {
            int kp0 = kk >> 1;
            const uint32_t* wrow = Wpk + (size_t)(kp0 + bkp) * COUT;
#pragma unroll
            for (int j = 0; j < 4; j++) {
                int col = bl16 + 16 * j;
                sm.mm.Bs[b][bkp][col] = wrow[col];
            }
        }
    };

    load_stage(0, 0);
#pragma unroll
    for (int ki = 0; ki < NKI; ki++) {
        int buf = ki & 1;
        __syncthreads();
        if (ki < NKI - 1) load_stage(ki + 1, buf ^ 1);
#pragma unroll
        for (int ks = 0; ks < 2; ks++) {
            int k0h = ks * 8;
            uint32_t af[2][4];
#pragma unroll
            for (int mt = 0; mt < 2; mt++) {
                int row = wm * 32 + mt * 16 + lg;
                af[mt][0] = sm.mm.As[buf][row][k0h + lt];
                af[mt][1] = sm.mm.As[buf][row + 8][k0h + lt];
                af[mt][2] = sm.mm.As[buf][row][k0h + lt + 4];
                af[mt][3] = sm.mm.As[buf][row + 8][k0h + lt + 4];
            }
            uint32_t bf[4][2];
#pragma unroll
            for (int nt = 0; nt < 4; nt++) {
                int col = wn * 32 + nt * 8 + lg;
                bf[nt][0] = sm.mm.Bs[buf][k0h + lt][col];
                bf[nt][1] = sm.mm.Bs[buf][k0h + lt + 4][col];
            }
#pragma unroll
            for (int mt = 0; mt < 2; mt++)
#pragma unroll
                for (int nt = 0; nt < 4; nt++)
                    mma_f16(c[mt][nt], af[mt], bf[nt]);
        }
    }
    __syncthreads();

#pragma unroll
    for (int mt = 0; mt < 2; mt++) {
        int rl = wm * 32 + mt * 16 + lg;
#pragma unroll
        for (int nt = 0; nt < 4; nt++) {
            int col = wn * 32 + nt * 8 + lt * 2;
            float b0 = bl[col], b1 = bl[col + 1];
            sm.logits[rl][col]         = c[mt][nt].x + b0;
            sm.logits[rl][col + 1]     = c[mt][nt].y + b1;
            sm.logits[rl + 8][col]     = c[mt][nt].z + b0;
            sm.logits[rl + 8][col + 1] = c[mt][nt].w + b1;
        }
    }
    __syncthreads();

    for (int r = wid * 16; r < wid * 16 + 16; r++) {
        int grow = rowBase + r;
        if (grow >= N) break;
        float v0 = sm.logits[r][lane];
        float v1 = sm.logits[r][lane + 32];
        float m = fmaxf(v0, v1);
#pragma unroll
        for (int o = 16; o; o >>= 1) m = fmaxf(m, __shfl_xor_sync(0xffffffffu, m, o));
        float s = expf(v0 - m) + expf(v1 - m);
#pragma unroll
        for (int o = 16; o; o >>= 1) s += __shfl_xor_sync(0xffffffffu, s, o);
        float ls = m + logf(s);
        out[(size_t)grow * COUT + lane]      = v0 - ls;
        out[(size_t)grow * COUT + lane + 32] = v1 - ls;
    }
}

// ---------------------------------------------------------------------------
// Single-pass per-node GAT, 2 edges per inner iteration.
// __launch_bounds__(256, 6): cap regs at 42 (current use 40) -> 6 CTAs/SM,
// occupancy 63% -> 75% for better L2-latency hiding.
// ---------------------------------------------------------------------------
__global__ void __launch_bounds__(256, 6)
node_gat(const __half* __restrict__ h16,
         const float* __restrict__ bias,
         __half* __restrict__ out, int N, int do_relu) {
    int d = (blockIdx.x * blockDim.x + threadIdx.x) >> 5;
    int lane = threadIdx.x & 31;
    if (d >= N) return;

    int beg = g_rowptr[d];
    int end = g_rowptr[d + 1];
    float sdst_d = g_sdst[d];
    float eself = g_es[d];           // hoisted: overlaps with loop latency

    int hl   = lane & 15;
    int side = lane >> 4;

    float den = 0.f;
    float acc[8];
#pragma unroll
    for (int k = 0; k < 8; k++) acc[k] = 0.f;

    for (int base = beg; base < end; base += 32) {
        int j = base + lane;
        float al = 0.f;
        int   sl = 0;
        if (j < end) {
            int s = g_csr_src[j];
            float e = g_ssrc[s] + sdst_d;
            e = e > 0.f ? e : 0.2f * e;
            al = __expf(e);
            sl = s;
        }
        den += al;
        int cnt = min(32, end - base);
        int npairs = (cnt + 1) >> 1;
#pragma unroll 4
        for (int p = 0; p < npairs; p++) {
            int idx = 2 * p + side;
            float a = __shfl_sync(0xffffffffu, al, idx);
            int   s = __shfl_sync(0xffffffffu, sl, idx);
            uint4 u = *(const uint4*)(h16 + (size_t)s * FEAT + hl * 8);
            float2 f0 = __half22float2(*(__half2*)&u.x);
            float2 f1 = __half22float2(*(__half2*)&u.y);
            float2 f2 = __half22float2(*(__half2*)&u.z);
            float2 f3 = __half22float2(*(__half2*)&u.w);
            acc[0] = fmaf(a, f0.x, acc[0]);
            acc[1] = fmaf(a, f0.y, acc[1]);
            acc[2] = fmaf(a, f1.x, acc[2]);
            acc[3] = fmaf(a, f1.y, acc[3]);
            acc[4] = fmaf(a, f2.x, acc[4]);
            acc[5] = fmaf(a, f2.y, acc[5]);
            acc[6] = fmaf(a, f3.x, acc[6]);
            acc[7] = fmaf(a, f3.y, acc[7]);
        }
    }

    // self row loaded early so its latency overlaps the reduction shfl chain
    uint4 su = *(const uint4*)(h16 + (size_t)d * FEAT + hl * 8);

#pragma unroll
    for (int k = 0; k < 8; k++)
        acc[k] += __shfl_xor_sync(0xffffffffu, acc[k], 16);

#pragma unroll
    for (int o = 16; o; o >>= 1) den += __shfl_xor_sync(0xffffffffu, den, o);

    float aself = __expf(eself);
    den += aself;
    float inv = 1.f / den;

    if (side == 0) {
        float2 s0 = __half22float2(*(__half2*)&su.x);
        float2 s1 = __half22float2(*(__half2*)&su.y);
        float2 s2 = __half22float2(*(__half2*)&su.z);
        float2 s3 = __half22float2(*(__half2*)&su.w);
        float4 b0 = *(const float4*)(bias + hl * 8);
        float4 b1 = *(const float4*)(bias + hl * 8 + 4);
        float o0 = fmaf(aself, s0.x, acc[0]) * inv + b0.x;
        float o1 = fmaf(aself, s0.y, acc[1]) * inv + b0.y;
        float o2 = fmaf(aself, s1.x, acc[2]) * inv + b0.z;
        float o3 = fmaf(aself, s1.y, acc[3]) * inv + b0.w;
        float o4 = fmaf(aself, s2.x, acc[4]) * inv + b1.x;
        float o5 = fmaf(aself, s2.y, acc[5]) * inv + b1.y;
        float o6 = fmaf(aself, s3.x, acc[6]) * inv + b1.z;
        float o7 = fmaf(aself, s3.y, acc[7]) * inv + b1.w;
        if (do_relu) {
            o0 = fmaxf(o0, 0.f); o1 = fmaxf(o1, 0.f);
            o2 = fmaxf(o2, 0.f); o3 = fmaxf(o3, 0.f);
            o4 = fmaxf(o4, 0.f); o5 = fmaxf(o5, 0.f);
            o6 = fmaxf(o6, 0.f); o7 = fmaxf(o7, 0.f);
        }
        uint4 po;
        po.x = pack_half2(o0, o1);
        po.y = pack_half2(o2, o3);
        po.z = pack_half2(o4, o5);
        po.w = pack_half2(o6, o7);
        *(uint4*)(out + (size_t)d * FEAT + hl * 8) = po;
    }
}

// ---------------------------------------------------------------------------
// Host orchestration
// ---------------------------------------------------------------------------
extern "C" void kernel_launch(void* const* d_in, const int* in_sizes, int n_in,
                              void* d_out, int out_size) {
    const float* x   = (const float*)d_in[0];
    const void*  ei  = d_in[1];
    const float* W1  = (const float*)d_in[2];
    const float* a1s = (const float*)d_in[3];
    const float* a1d = (const float*)d_in[4];
    const float* b1  = (const float*)d_in[5];
    const float* W2  = (const float*)d_in[6];
    const float* a2s = (const float*)d_in[7];
    const float* a2d = (const float*)d_in[8];
    const float* b2  = (const float*)d_in[9];
    const float* Wl  = (const float*)d_in[10];
    const float* bl  = (const float*)d_in[11];

    int N = in_sizes[0] / FEAT;
    int E = in_sizes[1] / 2;

    __half *h16, *o1, *o2;
    uint32_t *w1pk, *w2pk, *wlpk;
    void *pdeg, *pfill, *pbar;
    cudaGetSymbolAddress((void**)&h16,  g_h16);
    cudaGetSymbolAddress((void**)&o1,   g_o1);
    cudaGetSymbolAddress((void**)&o2,   g_o2);
    cudaGetSymbolAddress((void**)&w1pk, g_w1pk);
    cudaGetSymbolAddress((void**)&w2pk, g_w2pk);
    cudaGetSymbolAddress((void**)&wlpk, g_wlpk);
    cudaGetSymbolAddress(&pdeg,  g_deg);
    cudaGetSymbolAddress(&pfill, g_fill);
    cudaGetSymbolAddress(&pbar,  g_bar);

    long long extra = (long long)out_size - (long long)N * COUT;
    float* tailf = (extra == 2LL * E) ? (float*)d_out + (size_t)N * COUT : (float*)0;

    int ncheck = (2 * E < 2048) ? 2 * E : 2048;
    cudaMemsetAsync(pdeg,  0, (size_t)N * sizeof(int));
    cudaMemsetAsync(pfill, 0, (size_t)N * sizeof(int));
    cudaMemsetAsync(pbar,  0, 8 * sizeof(unsigned));

    // launch 1: pack weights; launch 2: fused CSR build
    pack_weights<<<(2 * 8192 + 4096 + 255) / 256, 256>>>(W1, W2, Wl);
    csr_build<<<CSR_BLOCKS, CSR_THREADS>>>(ei, N, E, ncheck, tailf);

    int ggrid = (N + GBM - 1) / GBM;

    // launches 3-4: layer 1
    gemm_f16<<<ggrid, 256>>>(x, 0, w1pk, a1s, a1d, h16, N);
    node_gat<<<(N * 32 + 255) / 256, 256>>>(h16, b1, o1, N, 1);

    // launches 5-6: layer 2 (launch 6 = node_gat, profiled by ncu -s 5)
    gemm_f16<<<ggrid, 256>>>(o1, 1, w2pk, a2s, a2d, h16, N);
    node_gat<<<(N * 32 + 255) / 256, 256>>>(h16, b2, o2, N, 0);

    // launch 7: fused final GEMM + bias + log-softmax
    gemm_f16_final<<<ggrid, 256>>>(o1, o2, wlpk, bl, (float*)d_out, N);

    if (extra == 4LL * E) {
        cudaMemcpyAsync((char*)d_out + (size_t)N * COUT * sizeof(float), ei,
                        sizeof(long long) * 2 * E, cudaMemcpyDeviceToDevice);
    }
}

// round 17
// speedup vs baseline: 1.0556x; 1.0556x over previous
#include <cuda_runtime.h>
#include <cuda_fp16.h>
#include <math.h>
#include <stdint.h>

#define MAXN   100000
#define MAXE   1600000
#define FEAT   128
#define COUT   64

#define CSR_BLOCKS  256
#define CSR_THREADS 512

// ---------------------------------------------------------------------------
// Scratch (device globals — no allocations allowed)
// ---------------------------------------------------------------------------
__device__ __half   g_h16[MAXN * FEAT];
__device__ __half   g_o1 [MAXN * FEAT];
__device__ __half   g_o2 [MAXN * FEAT];
__device__ float    g_ssrc[MAXN];
__device__ float    g_sdst[MAXN];
__device__ float    g_es  [MAXN];
__device__ int      g_edges[2 * MAXE];
__device__ int      g_rowptr[MAXN + 1];
__device__ int      g_csr_src[MAXE];
__device__ int      g_deg [MAXN];
__device__ int      g_fill[MAXN];
__device__ int      g_bsum[CSR_BLOCKS];
__device__ unsigned g_bar[8];
__device__ int      g_is64;
// k-pair-packed fp16 weights: Wpk[kp*cols + col] = half2(W[2kp][col], W[2kp+1][col])
__device__ uint32_t g_w1pk[(FEAT / 2) * FEAT];
__device__ uint32_t g_w2pk[(FEAT / 2) * FEAT];
__device__ uint32_t g_wlpk[(FEAT / 2) * COUT];

// ---------------------------------------------------------------------------
// fp16 / cp.async helpers
// ---------------------------------------------------------------------------
__device__ __forceinline__ uint32_t pack_half2(float a, float b) {
    __half2 h = __floats2half2_rn(a, b);
    return *reinterpret_cast<uint32_t*>(&h);
}

__device__ __forceinline__ uint32_t smem_u32(const void* p) {
    return (uint32_t)__cvta_generic_to_shared(p);
}
__device__ __forceinline__ void cp_async16(uint32_t dst, const void* src) {
    asm volatile("cp.async.cg.shared.global [%0], [%1], 16;" :: "r"(dst), "l"(src));
}
__device__ __forceinline__ void cp_async8(uint32_t dst, const void* src) {
    asm volatile("cp.async.ca.shared.global [%0], [%1], 8;" :: "r"(dst), "l"(src));
}
#define CP_COMMIT() asm volatile("cp.async.commit_group;" ::: "memory")
#define CP_WAIT0()  asm volatile("cp.async.wait_group 0;" ::: "memory")

// Pre-pack W1, W2 (128x128) and Wl (128x64) into k-pair fp16 layout. One launch.
__global__ void pack_weights(const float* __restrict__ W1,
                             const float* __restrict__ W2,
                             const float* __restrict__ Wl) {
    int i = blockIdx.x * blockDim.x + threadIdx.x;
    const int nW = (FEAT / 2) * FEAT;
    const int nL = (FEAT / 2) * COUT;
    if (i < nW) {
        int kp = i >> 7, col = i & 127;
        g_w1pk[i] = pack_half2(W1[(2 * kp) * FEAT + col], W1[(2 * kp + 1) * FEAT + col]);
    } else if (i < 2 * nW) {
        int j = i - nW;
        int kp = j >> 7, col = j & 127;
        g_w2pk[j] = pack_half2(W2[(2 * kp) * FEAT + col], W2[(2 * kp + 1) * FEAT + col]);
    } else if (i < 2 * nW + nL) {
        int j = i - 2 * nW;
        int kp = j >> 6, col = j & 63;
        g_wlpk[j] = pack_half2(Wl[(2 * kp) * COUT + col], Wl[(2 * kp + 1) * COUT + col]);
    }
}

// ---------------------------------------------------------------------------
// Fused CSR build (detect + convert + count + scan + fill + tail copy)
// ---------------------------------------------------------------------------
__device__ __forceinline__ void grid_barrier(int id) {
    __syncthreads();
    if (threadIdx.x == 0) {
        unsigned arrived = atomicAdd(&g_bar[id], 1u) + 1u;
        if (arrived < gridDim.x) {
            while (*(volatile unsigned*)&g_bar[id] < gridDim.x) __nanosleep(64);
        }
    }
    __syncthreads();
}

__global__ void __launch_bounds__(CSR_THREADS, 4)
csr_build(const void* ei, int N, int E, int ncheck, float* tailf) {
    __shared__ int swarp[CSR_THREADS / 32];
    const int tid = threadIdx.x;
    const int gid = blockIdx.x * CSR_THREADS + tid;
    const int stride = gridDim.x * CSR_THREADS;
    const int lane = tid & 31;
    const int warp = tid >> 5;

    int ok = 1;
    const long long* p64 = (const long long*)ei;
    for (int i = tid; i < ncheck; i += CSR_THREADS) {
        long long v = p64[i];
        if (v < 0 || v >= (long long)N) ok = 0;
    }
    const int is64 = __syncthreads_and(ok);
    if (gid == 0) g_is64 = is64;

    for (int i = gid; i < 2 * E; i += stride) {
        int v;
        if (is64) v = (int)p64[i];
        else      v = ((const int*)ei)[i];
        g_edges[i] = v;
        if (tailf) tailf[i] = (float)v;
        if (i >= E) atomicAdd(&g_deg[v], 1);
    }
    grid_barrier(0);

    int v = (gid < N) ? g_deg[gid] : 0;
    int x = v;
#pragma unroll
    for (int o = 1; o < 32; o <<= 1) {
        int y = __shfl_up_sync(0xffffffffu, x, o);
        if (lane >= o) x += y;
    }
    if (lane == 31) swarp[warp] = x;
    __syncthreads();
    if (warp == 0) {
        int s = (lane < CSR_THREADS / 32) ? swarp[lane] : 0;
#pragma unroll
        for (int o = 1; o < 32; o <<= 1) {
            int y = __shfl_up_sync(0xffffffffu, s, o);
            if (lane >= o) s += y;
        }
        if (lane < CSR_THREADS / 32) swarp[lane] = s;
    }
    __syncthreads();
    int incl = x + (warp ? swarp[warp - 1] : 0);
    if (tid == CSR_THREADS - 1) g_bsum[blockIdx.x] = incl;
    grid_barrier(1);

    {
        __shared__ int sred[CSR_THREADS / 32];
        int p = 0;
        for (int j = tid; j < (int)blockIdx.x; j += CSR_THREADS) p += g_bsum[j];
#pragma unroll
        for (int o = 16; o; o >>= 1) p += __shfl_xor_sync(0xffffffffu, p, o);
        if (lane == 0) sred[warp] = p;
        __syncthreads();
        if (warp == 0) {
            int q = (lane < CSR_THREADS / 32) ? sred[lane] : 0;
#pragma unroll
            for (int o = 16; o; o >>= 1) q += __shfl_xor_sync(0xffffffffu, q, o);
            if (lane == 0) sred[0] = q;
        }
        __syncthreads();
        int bpref = sred[0];
        if (gid < N) g_rowptr[gid] = bpref + incl - v;
        if (gid == N) g_rowptr[N] = E;
    }
    grid_barrier(2);

    for (int e = gid; e < E; e += stride) {
        int d = g_edges[E + e];
        int pos = g_rowptr[d] + atomicAdd(&g_fill[d], 1);
        g_csr_src[pos] = g_edges[e];
    }
}

// ---------------------------------------------------------------------------
// fp16 HMMA
// ---------------------------------------------------------------------------
__device__ __forceinline__ void mma_f16(float4& c, const uint32_t a[4], const uint32_t b[2]) {
    asm volatile(
        "mma.sync.aligned.m16n8k16.row.col.f32.f16.f16.f32 "
        "{%0,%1,%2,%3}, {%4,%5,%6,%7}, {%8,%9}, {%0,%1,%2,%3};\n"
        : "+f"(c.x), "+f"(c.y), "+f"(c.z), "+f"(c.w)
        : "r"(a[0]), "r"(a[1]), "r"(a[2]), "r"(a[3]), "r"(b[0]), "r"(b[1]));
}

#define GBM 128
#define GBK 32
#define NKI (FEAT / GBK)
#define ASTR 20
#define BSTR 136
#define BSTRF 72

// h16[N,128] = fp16(A[N,128] @ W[128,128]); fused scores.
// Double-buffered with cp.async: B always async (16B), A async when fp16.
__global__ void __launch_bounds__(256, 2)
gemm_f16(const void* __restrict__ A, int a_half,
         const uint32_t* __restrict__ Wpk,
         const float* __restrict__ a_src, const float* __restrict__ a_dst,
         __half* __restrict__ H16, int N) {
    __shared__ __align__(16) uint32_t As[2][GBM][ASTR];
    __shared__ __align__(16) uint32_t Bs[2][GBK / 2][BSTR];
    __shared__ float sAs[FEAT], sAd[FEAT];
    __shared__ float redS[GBM][2], redD[GBM][2];

    int t = threadIdx.x;
    int wid = t >> 5, lane = t & 31;
    int wm = wid >> 1, wn = wid & 1;
    int rowBase = blockIdx.x * GBM;
    int lg = lane >> 2;
    int lt = lane & 3;

    if (t < FEAT) { sAs[t] = a_src[t]; sAd[t] = a_dst[t]; }

    float4 c[2][8];
#pragma unroll
    for (int mt = 0; mt < 2; mt++)
#pragma unroll
        for (int nt = 0; nt < 8; nt++) c[mt][nt] = make_float4(0.f, 0.f, 0.f, 0.f);

    int arow = t >> 3;
    int acol = (t & 7) * 4;
    int bkp  = t >> 5;

    auto load_stage = [&](int ki, int b) {
        int kk = ki * GBK;
        if (a_half) {
#pragma unroll
            for (int v = 0; v < 4; v++) {
                int r = arow + v * 32;
                int gr = rowBase + r;
                if (gr < N) {
                    cp_async8(smem_u32(&As[b][r][acol >> 1]),
                              (const __half*)A + (size_t)gr * FEAT + kk + acol);
                } else {
                    As[b][r][(acol >> 1) + 0] = 0u;
                    As[b][r][(acol >> 1) + 1] = 0u;
                }
            }
        } else {
#pragma unroll
            for (int v = 0; v < 4; v++) {
                int r = arow + v * 32;
                int gr = rowBase + r;
                float4 av = make_float4(0.f, 0.f, 0.f, 0.f);
                if (gr < N) av = *(const float4*)((const float*)A + (size_t)gr * FEAT + kk + acol);
                As[b][r][(acol >> 1) + 0] = pack_half2(av.x, av.y);
                As[b][r][(acol >> 1) + 1] = pack_half2(av.z, av.w);
            }
        }
        int kp0 = kk >> 1;
#pragma unroll
        for (int v = 0; v < 2; v++) {
            int kp = bkp + v * 8;
            cp_async16(smem_u32(&Bs[b][kp][lane * 4]),
                       Wpk + (size_t)(kp0 + kp) * FEAT + lane * 4);
        }
    };

    load_stage(0, 0);
    CP_COMMIT();
#pragma unroll
    for (int ki = 0; ki < NKI; ki++) {
        int buf = ki & 1;
        CP_WAIT0();
        __syncthreads();
        if (ki < NKI - 1) { load_stage(ki + 1, buf ^ 1); CP_COMMIT(); }
#pragma unroll
        for (int ks = 0; ks < 2; ks++) {
            int k0h = ks * 8;
            uint32_t af[2][4];
#pragma unroll
            for (int mt = 0; mt < 2; mt++) {
                int row = wm * 32 + mt * 16 + lg;
                af[mt][0] = As[buf][row][k0h + lt];
                af[mt][1] = As[buf][row + 8][k0h + lt];
                af[mt][2] = As[buf][row][k0h + lt + 4];
                af[mt][3] = As[buf][row + 8][k0h + lt + 4];
            }
            uint32_t bf[8][2];
#pragma unroll
            for (int nt = 0; nt < 8; nt++) {
                int col = wn * 64 + nt * 8 + lg;
                bf[nt][0] = Bs[buf][k0h + lt][col];
                bf[nt][1] = Bs[buf][k0h + lt + 4][col];
            }
#pragma unroll
            for (int mt = 0; mt < 2; mt++)
#pragma unroll
                for (int nt = 0; nt < 8; nt++)
                    mma_f16(c[mt][nt], af[mt], bf[nt]);
        }
    }

    // epilogue: fp16 store + fused score partials
#pragma unroll
    for (int mt = 0; mt < 2; mt++) {
        int rl0 = wm * 32 + mt * 16 + lg;
        int row0 = rowBase + rl0;
        float pS0 = 0.f, pS8 = 0.f, pD0 = 0.f, pD8 = 0.f;
#pragma unroll
        for (int nt = 0; nt < 8; nt++) {
            int col = wn * 64 + nt * 8 + lt * 2;
            float as0 = sAs[col], as1 = sAs[col + 1];
            float ad0 = sAd[col], ad1 = sAd[col + 1];
            pS0 += c[mt][nt].x * as0 + c[mt][nt].y * as1;
            pD0 += c[mt][nt].x * ad0 + c[mt][nt].y * ad1;
            pS8 += c[mt][nt].z * as0 + c[mt][nt].w * as1;
            pD8 += c[mt][nt].z * ad0 + c[mt][nt].w * ad1;
            if (row0 < N)
                *(__half2*)(H16 + (size_t)row0 * FEAT + col) = __floats2half2_rn(c[mt][nt].x, c[mt][nt].y);
            if (row0 + 8 < N)
                *(__half2*)(H16 + (size_t)(row0 + 8) * FEAT + col) = __floats2half2_rn(c[mt][nt].z, c[mt][nt].w);
        }
#pragma unroll
        for (int o = 1; o < 4; o <<= 1) {
            pS0 += __shfl_xor_sync(0xffffffffu, pS0, o);
            pS8 += __shfl_xor_sync(0xffffffffu, pS8, o);
            pD0 += __shfl_xor_sync(0xffffffffu, pD0, o);
            pD8 += __shfl_xor_sync(0xffffffffu, pD8, o);
        }
        if (lt == 0) {
            redS[rl0][wn] = pS0;      redD[rl0][wn] = pD0;
            redS[rl0 + 8][wn] = pS8;  redD[rl0 + 8][wn] = pD8;
        }
    }
    __syncthreads();
    if (t < GBM) {
        int grow = rowBase + t;
        if (grow < N) {
            float s1 = redS[t][0] + redS[t][1];
            float s2 = redD[t][0] + redD[t][1];
            g_ssrc[grow] = s1;
            g_sdst[grow] = s2;
            float e = s1 + s2;
            g_es[grow] = e > 0.f ? e : 0.2f * e;
        }
    }
}

// ---------------------------------------------------------------------------
// Final: L = (o1+o2) @ Wl + bl, fused log-softmax. Double-buffered, Wl packed.
// (unchanged from the 250.1us config)
// ---------------------------------------------------------------------------
__global__ void __launch_bounds__(256, 2)
gemm_f16_final(const __half* __restrict__ A1, const __half* __restrict__ A2,
               const uint32_t* __restrict__ Wpk, const float* __restrict__ bl,
               float* __restrict__ out, int N) {
    __shared__ union SmU {
        struct { uint32_t As[2][GBM][ASTR]; uint32_t Bs[2][GBK / 2][BSTRF]; } mm;
        float logits[GBM][COUT + 2];
    } sm;

    int t = threadIdx.x;
    int wid = t >> 5, lane = t & 31;
    int wm = wid >> 1, wn = wid & 1;
    int rowBase = blockIdx.x * GBM;
    int lg = lane >> 2;
    int lt = lane & 3;

    float4 c[2][4];
#pragma unroll
    for (int mt = 0; mt < 2; mt++)
#pragma unroll
        for (int nt = 0; nt < 4; nt++) c[mt][nt] = make_float4(0.f, 0.f, 0.f, 0.f);

    int arow = t >> 3;
    int acol = (t & 7) * 4;
    int bkp  = t >> 4;
    int bl16 = t & 15;

    auto load_stage = [&](int ki, int b) {
        int kk = ki * GBK;
#pragma unroll
        for (int v = 0; v < 4; v++) {
            int r = arow + v * 32;
            int gr = rowBase + r;
            uint32_t p0 = 0u, p1 = 0u;
            if (gr < N) {
                uint2 u1 = *(const uint2*)(A1 + (size_t)gr * FEAT + kk + acol);
                uint2 u2 = *(const uint2*)(A2 + (size_t)gr * FEAT + kk + acol);
                float2 a0 = __half22float2(*(__half2*)&u1.x);
                float2 a1 = __half22float2(*(__half2*)&u1.y);
                float2 b0 = __half22float2(*(__half2*)&u2.x);
                float2 b1 = __half22float2(*(__half2*)&u2.y);
                p0 = pack_half2(a0.x + b0.x, a0.y + b0.y);
                p1 = pack_half2(a1.x + b1.x, a1.y + b1.y);
            }
            sm.mm.As[b][r][(acol >> 1) + 0] = p0;
            sm.mm.As[b][r][(acol >> 1) + 1] = p1;
        }
        {
            int kp0 = kk >> 1;
            const uint32_t* wrow = Wpk + (size_t)(kp0 + bkp) * COUT;
#pragma unroll
            for (int j = 0; j < 4; j++) {
                int col = bl16 + 16 * j;
                sm.mm.Bs[b][bkp][col] = wrow[col];
            }
        }
    };

    load_stage(0, 0);
#pragma unroll
    for (int ki = 0; ki < NKI; ki++) {
        int buf = ki & 1;
        __syncthreads();
        if (ki < NKI - 1) load_stage(ki + 1, buf ^ 1);
#pragma unroll
        for (int ks = 0; ks < 2; ks++) {
            int k0h = ks * 8;
            uint32_t af[2][4];
#pragma unroll
            for (int mt = 0; mt < 2; mt++) {
                int row = wm * 32 + mt * 16 + lg;
                af[mt][0] = sm.mm.As[buf][row][k0h + lt];
                af[mt][1] = sm.mm.As[buf][row + 8][k0h + lt];
                af[mt][2] = sm.mm.As[buf][row][k0h + lt + 4];
                af[mt][3] = sm.mm.As[buf][row + 8][k0h + lt + 4];
            }
            uint32_t bf[4][2];
#pragma unroll
            for (int nt = 0; nt < 4; nt++) {
                int col = wn * 32 + nt * 8 + lg;
                bf[nt][0] = sm.mm.Bs[buf][k0h + lt][col];
                bf[nt][1] = sm.mm.Bs[buf][k0h + lt + 4][col];
            }
#pragma unroll
            for (int mt = 0; mt < 2; mt++)
#pragma unroll
                for (int nt = 0; nt < 4; nt++)
                    mma_f16(c[mt][nt], af[mt], bf[nt]);
        }
    }
    __syncthreads();

#pragma unroll
    for (int mt = 0; mt < 2; mt++) {
        int rl = wm * 32 + mt * 16 + lg;
#pragma unroll
        for (int nt = 0; nt < 4; nt++) {
            int col = wn * 32 + nt * 8 + lt * 2;
            float b0 = bl[col], b1 = bl[col + 1];
            sm.logits[rl][col]         = c[mt][nt].x + b0;
            sm.logits[rl][col + 1]     = c[mt][nt].y + b1;
            sm.logits[rl + 8][col]     = c[mt][nt].z + b0;
            sm.logits[rl + 8][col + 1] = c[mt][nt].w + b1;
        }
    }
    __syncthreads();

    for (int r = wid * 16; r < wid * 16 + 16; r++) {
        int grow = rowBase + r;
        if (grow >= N) break;
        float v0 = sm.logits[r][lane];
        float v1 = sm.logits[r][lane + 32];
        float m = fmaxf(v0, v1);
#pragma unroll
        for (int o = 16; o; o >>= 1) m = fmaxf(m, __shfl_xor_sync(0xffffffffu, m, o));
        float s = expf(v0 - m) + expf(v1 - m);
#pragma unroll
        for (int o = 16; o; o >>= 1) s += __shfl_xor_sync(0xffffffffu, s, o);
        float ls = m + logf(s);
        out[(size_t)grow * COUT + lane]      = v0 - ls;
        out[(size_t)grow * COUT + lane + 32] = v1 - ls;
    }
}

// ---------------------------------------------------------------------------
// Single-pass per-node GAT, 2 edges per inner iteration (R14-exact revert).
// ---------------------------------------------------------------------------
__global__ void node_gat(const __half* __restrict__ h16,
                         const float* __restrict__ bias,
                         __half* __restrict__ out, int N, int do_relu) {
    int d = (blockIdx.x * blockDim.x + threadIdx.x) >> 5;
    int lane = threadIdx.x & 31;
    if (d >= N) return;

    int beg = g_rowptr[d];
    int end = g_rowptr[d + 1];
    float sdst_d = g_sdst[d];

    int hl   = lane & 15;
    int side = lane >> 4;

    float den = 0.f;
    float acc[8];
#pragma unroll
    for (int k = 0; k < 8; k++) acc[k] = 0.f;

    for (int base = beg; base < end; base += 32) {
        int j = base + lane;
        float al = 0.f;
        int   sl = 0;
        if (j < end) {
            int s = g_csr_src[j];
            float e = g_ssrc[s] + sdst_d;
            e = e > 0.f ? e : 0.2f * e;
            al = __expf(e);
            sl = s;
        }
        den += al;
        int cnt = min(32, end - base);
        int npairs = (cnt + 1) >> 1;
#pragma unroll 4
        for (int p = 0; p < npairs; p++) {
            int idx = 2 * p + side;
            float a = __shfl_sync(0xffffffffu, al, idx);
            int   s = __shfl_sync(0xffffffffu, sl, idx);
            uint4 u = *(const uint4*)(h16 + (size_t)s * FEAT + hl * 8);
            float2 f0 = __half22float2(*(__half2*)&u.x);
            float2 f1 = __half22float2(*(__half2*)&u.y);
            float2 f2 = __half22float2(*(__half2*)&u.z);
            float2 f3 = __half22float2(*(__half2*)&u.w);
            acc[0] = fmaf(a, f0.x, acc[0]);
            acc[1] = fmaf(a, f0.y, acc[1]);
            acc[2] = fmaf(a, f1.x, acc[2]);
            acc[3] = fmaf(a, f1.y, acc[3]);
            acc[4] = fmaf(a, f2.x, acc[4]);
            acc[5] = fmaf(a, f2.y, acc[5]);
            acc[6] = fmaf(a, f3.x, acc[6]);
            acc[7] = fmaf(a, f3.y, acc[7]);
        }
    }

#pragma unroll
    for (int k = 0; k < 8; k++)
        acc[k] += __shfl_xor_sync(0xffffffffu, acc[k], 16);

#pragma unroll
    for (int o = 16; o; o >>= 1) den += __shfl_xor_sync(0xffffffffu, den, o);

    float aself = __expf(g_es[d]);
    den += aself;
    float inv = 1.f / den;

    if (side == 0) {
        uint4 su = *(const uint4*)(h16 + (size_t)d * FEAT + hl * 8);
        float2 s0 = __half22float2(*(__half2*)&su.x);
        float2 s1 = __half22float2(*(__half2*)&su.y);
        float2 s2 = __half22float2(*(__half2*)&su.z);
        float2 s3 = __half22float2(*(__half2*)&su.w);
        float4 b0 = *(const float4*)(bias + hl * 8);
        float4 b1 = *(const float4*)(bias + hl * 8 + 4);
        float o0 = fmaf(aself, s0.x, acc[0]) * inv + b0.x;
        float o1 = fmaf(aself, s0.y, acc[1]) * inv + b0.y;
        float o2 = fmaf(aself, s1.x, acc[2]) * inv + b0.z;
        float o3 = fmaf(aself, s1.y, acc[3]) * inv + b0.w;
        float o4 = fmaf(aself, s2.x, acc[4]) * inv + b1.x;
        float o5 = fmaf(aself, s2.y, acc[5]) * inv + b1.y;
        float o6 = fmaf(aself, s3.x, acc[6]) * inv + b1.z;
        float o7 = fmaf(aself, s3.y, acc[7]) * inv + b1.w;
        if (do_relu) {
            o0 = fmaxf(o0, 0.f); o1 = fmaxf(o1, 0.f);
            o2 = fmaxf(o2, 0.f); o3 = fmaxf(o3, 0.f);
            o4 = fmaxf(o4, 0.f); o5 = fmaxf(o5, 0.f);
            o6 = fmaxf(o6, 0.f); o7 = fmaxf(o7, 0.f);
        }
        uint4 po;
        po.x = pack_half2(o0, o1);
        po.y = pack_half2(o2, o3);
        po.z = pack_half2(o4, o5);
        po.w = pack_half2(o6, o7);
        *(uint4*)(out + (size_t)d * FEAT + hl * 8) = po;
    }
}

// ---------------------------------------------------------------------------
// Host orchestration
// ---------------------------------------------------------------------------
extern "C" void kernel_launch(void* const* d_in, const int* in_sizes, int n_in,
                              void* d_out, int out_size) {
    const float* x   = (const float*)d_in[0];
    const void*  ei  = d_in[1];
    const float* W1  = (const float*)d_in[2];
    const float* a1s = (const float*)d_in[3];
    const float* a1d = (const float*)d_in[4];
    const float* b1  = (const float*)d_in[5];
    const float* W2  = (const float*)d_in[6];
    const float* a2s = (const float*)d_in[7];
    const float* a2d = (const float*)d_in[8];
    const float* b2  = (const float*)d_in[9];
    const float* Wl  = (const float*)d_in[10];
    const float* bl  = (const float*)d_in[11];

    int N = in_sizes[0] / FEAT;
    int E = in_sizes[1] / 2;

    __half *h16, *o1, *o2;
    uint32_t *w1pk, *w2pk, *wlpk;
    void *pdeg, *pfill, *pbar;
    cudaGetSymbolAddress((void**)&h16,  g_h16);
    cudaGetSymbolAddress((void**)&o1,   g_o1);
    cudaGetSymbolAddress((void**)&o2,   g_o2);
    cudaGetSymbolAddress((void**)&w1pk, g_w1pk);
    cudaGetSymbolAddress((void**)&w2pk, g_w2pk);
    cudaGetSymbolAddress((void**)&wlpk, g_wlpk);
    cudaGetSymbolAddress(&pdeg,  g_deg);
    cudaGetSymbolAddress(&pfill, g_fill);
    cudaGetSymbolAddress(&pbar,  g_bar);

    long long extra = (long long)out_size - (long long)N * COUT;
    float* tailf = (extra == 2LL * E) ? (float*)d_out + (size_t)N * COUT : (float*)0;

    int ncheck = (2 * E < 2048) ? 2 * E : 2048;
    cudaMemsetAsync(pdeg,  0, (size_t)N * sizeof(int));
    cudaMemsetAsync(pfill, 0, (size_t)N * sizeof(int));
    cudaMemsetAsync(pbar,  0, 8 * sizeof(unsigned));

    // launch 1: pack weights; launch 2: fused CSR build
    pack_weights<<<(2 * 8192 + 4096 + 255) / 256, 256>>>(W1, W2, Wl);
    csr_build<<<CSR_BLOCKS, CSR_THREADS>>>(ei, N, E, ncheck, tailf);

    int ggrid = (N + GBM - 1) / GBM;

    // launches 3-4: layer 1
    gemm_f16<<<ggrid, 256>>>(x, 0, w1pk, a1s, a1d, h16, N);
    node_gat<<<(N * 32 + 255) / 256, 256>>>(h16, b1, o1, N, 1);

    // launches 5-6: layer 2 (launch 6 = node_gat, profiled by ncu -s 5)
    gemm_f16<<<ggrid, 256>>>(o1, 1, w2pk, a2s, a2d, h16, N);
    node_gat<<<(N * 32 + 255) / 256, 256>>>(h16, b2, o2, N, 0);

    // launch 7: fused final GEMM + bias + log-softmax
    gemm_f16_final<<<ggrid, 256>>>(o1, o2, wlpk, bl, (float*)d_out, N);

    if (extra == 4LL * E) {
        cudaMemcpyAsync((char*)d_out + (size_t)N * COUT * sizeof(float), ei,
                        sizeof(long long) * 2 * E, cudaMemcpyDeviceToDevice);
    }
}